// round 1
// baseline (speedup 1.0000x reference)
#include <cuda_runtime.h>
#include <cuda_bf16.h>

// ---------------------------------------------------------------------------
// ParallelTransportAttention  (B=2, S=256, D=512, H=8, Dh=64, df=32, rank=8)
//
// Pipeline:
//   1) expm_kernel : A = 0.1*sum_r c_r G_r ; T = expm(A) (scale&square+Taylor);
//                    M = T^T T            -> g M [B*S,32,32]
//   2) hol_kernel  : hol(i,j) = sqrt(tr((Mi Mj)^2) - 2 tr(Mi Mj) + 32), sym,
//                    0 on diag            -> g hol [B,S,S]
//   3) sgemm x3    : Q/K/V projections
//   4) scores      : (Q K^T)/8 - lambda*hol
//   5) softmax     : + per-row  sum(attn*hol) partials
//   6) sgemm       : attn @ V  (batched per z,h)
//   7) sgemm       : @ Wo + bo            -> d_out[0 : 262144]
//   8) avg_kernel  : mean over heads
//   9) sgemm       : avg_attn @ fiber     (batched per z)
//  10) ns_kernel   : Newton-Schulz polar  -> d_out[262144 : 786432]
//  11) total       : reduce partials      -> d_out[786432]
// ---------------------------------------------------------------------------

#define B_  2
#define S_  256
#define D_  512
#define H_  8
#define DH_ 64
#define DF_ 32

// single scratch arena (float):
//   M       524288
//   hol     131072
//   Q       262144
//   K       262144
//   V       262144
//   attn   1048576
//   avg     131072
//   outpre  262144
//   fpre    524288
//   rowpart   4096
__device__ __align__(256) float g_scratch[3411968];

// ======================= 1) matrix exponential + M ==========================
__global__ __launch_bounds__(1024) void expm_kernel(
    const float* __restrict__ conn, const float* __restrict__ gen,
    float* __restrict__ Mout)
{
    __shared__ float sA[32][33], sP[32][33], sT[32][33], sW[32][33];
    __shared__ float scol[32];
    __shared__ int   s_s;
    int zs = blockIdx.x;            // 0..511
    int t  = threadIdx.x;           // 0..1023
    int a = t >> 5, b = t & 31;

    // A = 0.1 * sum_r c_r * G_r
    const float* c8 = conn + zs * 8;
    float acc = 0.f;
#pragma unroll
    for (int r = 0; r < 8; r++) acc += c8[r] * gen[r * 1024 + t];
    acc *= 0.1f;
    sA[a][b] = acc;
    sW[a][b] = fabsf(acc);
    __syncthreads();

    // 1-norm (max column abs sum)
    if (t < 32) {
        float cs = 0.f;
#pragma unroll
        for (int q = 0; q < 32; q++) cs += sW[q][t];
        scol[t] = cs;
    }
    __syncthreads();
    if (t == 0) {
        float nrm = 0.f;
#pragma unroll
        for (int q = 0; q < 32; q++) nrm = fmaxf(nrm, scol[q]);
        int s = 0;
        while (nrm > 0.25f * exp2f((float)s) && s < 12) s++;
        s_s = s;
    }
    __syncthreads();
    int   s  = s_s;
    float sc = exp2f((float)(-s));
    float aab = sA[a][b] * sc;
    __syncthreads();
    sA[a][b] = aab;
    sP[a][b] = aab;
    sT[a][b] = aab + ((a == b) ? 1.f : 0.f);
    __syncthreads();

    // Taylor terms A^2/2! .. A^9/9!
    for (int k = 2; k <= 9; k++) {
        float d = 0.f;
#pragma unroll
        for (int j = 0; j < 32; j++) d += sP[a][j] * sA[j][b];
        d *= (1.f / (float)k);
        __syncthreads();
        sP[a][b] = d;
        sT[a][b] += d;
        __syncthreads();
    }
    // squaring
    for (int it = 0; it < s; it++) {
        float d = 0.f;
#pragma unroll
        for (int j = 0; j < 32; j++) d += sT[a][j] * sT[j][b];
        __syncthreads();
        sT[a][b] = d;
        __syncthreads();
    }
    // M = T^T T
    float m = 0.f;
#pragma unroll
    for (int k2 = 0; k2 < 32; k2++) m += sT[k2][a] * sT[k2][b];
    Mout[zs * 1024 + t] = m;
}

// ======================= 2) pairwise holonomy ===============================
// warp handles one (i,j) pair: P = Mi*Mj, t1=tr(P), t2=tr(P^2)
__global__ __launch_bounds__(128) void hol_kernel(
    const float* __restrict__ Mg, float* __restrict__ hol)
{
    __shared__ float sMi[32][32];
    __shared__ float sP[4][32][33];
    int i = blockIdx.y, z = blockIdx.z, jt = blockIdx.x;
    int t = threadIdx.x;
    int w = t >> 5, lane = t & 31;

    // Mi -> smem (shared by 4 warps)
    const float4* mi4  = (const float4*)(Mg + (size_t)(z * 256 + i) * 1024);
    float4*       sMiv = (float4*)&sMi[0][0];
    for (int q = t; q < 256; q += 128) sMiv[q] = mi4[q];
    __syncthreads();

    int j = jt * 4 + w;
    if (j < i) return;                       // symmetry: only j >= i
    if (j == i) {
        if (lane == 0) hol[((size_t)(z * 256 + i)) * 256 + i] = 0.f;
        return;
    }

    // column `lane` of Mj == row `lane` (Mj symmetric)
    float mj[32];
    const float4* mj4 = (const float4*)(Mg + (size_t)(z * 256 + j) * 1024 + lane * 32);
#pragma unroll
    for (int q = 0; q < 8; q++) {
        float4 v = mj4[q];
        mj[4*q] = v.x; mj[4*q+1] = v.y; mj[4*q+2] = v.z; mj[4*q+3] = v.w;
    }

    float p[32];
    float t1 = 0.f;
    const float4* smi4 = (const float4*)&sMi[0][0];
#pragma unroll
    for (int a2 = 0; a2 < 32; a2++) {
        float acc = 0.f;
#pragma unroll
        for (int q = 0; q < 8; q++) {
            float4 m = smi4[a2 * 8 + q];     // broadcast
            acc += m.x * mj[4*q] + m.y * mj[4*q+1] + m.z * mj[4*q+2] + m.w * mj[4*q+3];
        }
        p[a2] = acc;                          // P[a2][lane]
        sP[w][a2][lane] = acc;
        if (a2 == lane) t1 = acc;             // diagonal
    }
    __syncwarp();
    float t2 = 0.f;
#pragma unroll
    for (int a2 = 0; a2 < 32; a2++) t2 += p[a2] * sP[w][lane][a2];

#pragma unroll
    for (int off = 16; off; off >>= 1) {
        t1 += __shfl_down_sync(0xffffffffu, t1, off);
        t2 += __shfl_down_sync(0xffffffffu, t2, off);
    }
    if (lane == 0) {
        float h2 = t2 - 2.f * t1 + 32.f;
        float h  = sqrtf(fmaxf(h2, 0.f));
        hol[((size_t)(z * 256 + i)) * 256 + j] = h;
        hol[((size_t)(z * 256 + j)) * 256 + i] = h;
    }
}

// ======================= generic strided-batched SGEMM (NN) =================
// C = A@B (+bias). 64x64x16 tiles, 256 threads, 4x4 register tile.
// per-batch offsets: off = (bz/bdiv)*s1 + (bz%bdiv)*s2
__global__ __launch_bounds__(256) void sgemm_nn(
    const float* __restrict__ A, const float* __restrict__ B,
    const float* __restrict__ bias, float* __restrict__ C,
    int K, int lda, int ldb, int ldc, int bdiv,
    long sA1, long sA2, long sB1, long sB2, long sC1, long sC2)
{
    __shared__ float As[16][68];
    __shared__ float Bs[16][68];
    int bz = blockIdx.z;
    A += (long)(bz / bdiv) * sA1 + (long)(bz % bdiv) * sA2;
    B += (long)(bz / bdiv) * sB1 + (long)(bz % bdiv) * sB2;
    C += (long)(bz / bdiv) * sC1 + (long)(bz % bdiv) * sC2;

    int t  = threadIdx.x;
    int tx = t & 15, ty = t >> 4;
    int row0 = blockIdx.y * 64, col0 = blockIdx.x * 64;
    int arow = t >> 2, acol = (t & 3) * 4;
    int brow = t >> 4, bcol = (t & 15) * 4;

    float acc[4][4] = {};
    for (int kk = 0; kk < K; kk += 16) {
        float4 av = *(const float4*)(A + (long)(row0 + arow) * lda + kk + acol);
        float4 bv = *(const float4*)(B + (long)(kk + brow) * ldb + col0 + bcol);
        __syncthreads();
        As[acol+0][arow] = av.x; As[acol+1][arow] = av.y;
        As[acol+2][arow] = av.z; As[acol+3][arow] = av.w;
        *(float4*)&Bs[brow][bcol] = bv;
        __syncthreads();
#pragma unroll
        for (int k = 0; k < 16; k++) {
            float4 a4 = *(const float4*)&As[k][ty * 4];
            float4 b4 = *(const float4*)&Bs[k][tx * 4];
            acc[0][0] += a4.x*b4.x; acc[0][1] += a4.x*b4.y; acc[0][2] += a4.x*b4.z; acc[0][3] += a4.x*b4.w;
            acc[1][0] += a4.y*b4.x; acc[1][1] += a4.y*b4.y; acc[1][2] += a4.y*b4.z; acc[1][3] += a4.y*b4.w;
            acc[2][0] += a4.z*b4.x; acc[2][1] += a4.z*b4.y; acc[2][2] += a4.z*b4.z; acc[2][3] += a4.z*b4.w;
            acc[3][0] += a4.w*b4.x; acc[3][1] += a4.w*b4.y; acc[3][2] += a4.w*b4.z; acc[3][3] += a4.w*b4.w;
        }
    }
    float bv4[4] = {0.f, 0.f, 0.f, 0.f};
    if (bias) {
#pragma unroll
        for (int j = 0; j < 4; j++) bv4[j] = bias[col0 + tx * 4 + j];
    }
#pragma unroll
    for (int ii = 0; ii < 4; ii++) {
        float4 o;
        o.x = acc[ii][0] + bv4[0]; o.y = acc[ii][1] + bv4[1];
        o.z = acc[ii][2] + bv4[2]; o.w = acc[ii][3] + bv4[3];
        *(float4*)(C + (long)(row0 + ty * 4 + ii) * ldc + col0 + tx * 4) = o;
    }
}

// ======================= 4) scores = QK^T/8 - lambda*hol ====================
__global__ __launch_bounds__(256) void scores_kernel(
    const float* __restrict__ Qm, const float* __restrict__ Km,
    const float* __restrict__ hol, const float* __restrict__ lam,
    float* __restrict__ Sout)
{
    __shared__ float As[16][68];
    __shared__ float Bs[16][68];
    int zh = blockIdx.z, z = zh >> 3, h = zh & 7;
    const float* Ab = Qm + (long)z * 256 * 512 + h * 64;
    const float* Bb = Km + (long)z * 256 * 512 + h * 64;
    int t  = threadIdx.x;
    int tx = t & 15, ty = t >> 4;
    int i0 = blockIdx.y * 64, j0 = blockIdx.x * 64;
    int arow = t >> 2, acol = (t & 3) * 4;

    float acc[4][4] = {};
    for (int kk = 0; kk < 64; kk += 16) {
        float4 av = *(const float4*)(Ab + (long)(i0 + arow) * 512 + kk + acol);
        float4 bv = *(const float4*)(Bb + (long)(j0 + arow) * 512 + kk + acol);
        __syncthreads();
        As[acol+0][arow] = av.x; As[acol+1][arow] = av.y;
        As[acol+2][arow] = av.z; As[acol+3][arow] = av.w;
        Bs[acol+0][arow] = bv.x; Bs[acol+1][arow] = bv.y;
        Bs[acol+2][arow] = bv.z; Bs[acol+3][arow] = bv.w;
        __syncthreads();
#pragma unroll
        for (int k = 0; k < 16; k++) {
            float4 a4 = *(const float4*)&As[k][ty * 4];
            float4 b4 = *(const float4*)&Bs[k][tx * 4];
            acc[0][0] += a4.x*b4.x; acc[0][1] += a4.x*b4.y; acc[0][2] += a4.x*b4.z; acc[0][3] += a4.x*b4.w;
            acc[1][0] += a4.y*b4.x; acc[1][1] += a4.y*b4.y; acc[1][2] += a4.y*b4.z; acc[1][3] += a4.y*b4.w;
            acc[2][0] += a4.z*b4.x; acc[2][1] += a4.z*b4.y; acc[2][2] += a4.z*b4.z; acc[2][3] += a4.z*b4.w;
            acc[3][0] += a4.w*b4.x; acc[3][1] += a4.w*b4.y; acc[3][2] += a4.w*b4.z; acc[3][3] += a4.w*b4.w;
        }
    }
    float l = __ldg(lam);
#pragma unroll
    for (int ii = 0; ii < 4; ii++) {
        int irow = i0 + ty * 4 + ii;
#pragma unroll
        for (int jj = 0; jj < 4; jj++) {
            int jcol = j0 + tx * 4 + jj;
            float v = acc[ii][jj] * 0.125f
                    - l * hol[((size_t)(z * 256 + irow)) * 256 + jcol];
            Sout[(size_t)zh * 65536 + (size_t)irow * 256 + jcol] = v;
        }
    }
}

// ======================= 5) softmax + hol partials ==========================
__global__ __launch_bounds__(256) void softmax_kernel(
    float* __restrict__ Sm, const float* __restrict__ hol,
    float* __restrict__ rowpart)
{
    __shared__ float red[8];
    __shared__ float bval;
    int row = blockIdx.x;              // (z*8+h)*256 + i
    int z = row >> 11;
    int i = row & 255;
    int t = threadIdx.x;
    int w = t >> 5, lane = t & 31;

    float v = Sm[(size_t)row * 256 + t];
    float m = v;
#pragma unroll
    for (int o = 16; o; o >>= 1) m = fmaxf(m, __shfl_xor_sync(0xffffffffu, m, o));
    if (lane == 0) red[w] = m;
    __syncthreads();
    if (t == 0) {
        float mm = red[0];
#pragma unroll
        for (int q = 1; q < 8; q++) mm = fmaxf(mm, red[q]);
        bval = mm;
    }
    __syncthreads();
    float e  = expf(v - bval);
    float ss = e;
#pragma unroll
    for (int o = 16; o; o >>= 1) ss += __shfl_xor_sync(0xffffffffu, ss, o);
    __syncthreads();
    if (lane == 0) red[w] = ss;
    __syncthreads();
    if (t == 0) {
        float s2 = 0.f;
#pragma unroll
        for (int q = 0; q < 8; q++) s2 += red[q];
        bval = s2;
    }
    __syncthreads();
    float at = e / bval;
    Sm[(size_t)row * 256 + t] = at;

    float hp = at * hol[((size_t)(z * 256 + i)) * 256 + t];
#pragma unroll
    for (int o = 16; o; o >>= 1) hp += __shfl_xor_sync(0xffffffffu, hp, o);
    __syncthreads();
    if (lane == 0) red[w] = hp;
    __syncthreads();
    if (t == 0) {
        float s3 = 0.f;
#pragma unroll
        for (int q = 0; q < 8; q++) s3 += red[q];
        rowpart[row] = s3;
    }
}

// ======================= 8) head-average of attn ============================
__global__ __launch_bounds__(256) void avg_kernel(
    const float* __restrict__ attn, float* __restrict__ avg)
{
    size_t idx = (size_t)blockIdx.x * 256 + threadIdx.x;   // 0..131071
    size_t z  = idx >> 16;
    size_t ij = idx & 65535;
    float s = 0.f;
#pragma unroll
    for (int h = 0; h < 8; h++) s += attn[(z * 8 + h) * 65536 + ij];
    avg[idx] = s * 0.125f;
}

// ======================= 10) Newton-Schulz polar factor =====================
__global__ __launch_bounds__(1024) void ns_kernel(
    const float* __restrict__ Fin, float* __restrict__ Fout)
{
    __shared__ float X[32][33], Sm[32][33];
    __shared__ float wred[32];
    __shared__ float s_scale;
    __shared__ int   s_flag;
    int zi = blockIdx.x;
    int t  = threadIdx.x;
    int a = t >> 5, b = t & 31, lane = t & 31, w = t >> 5;

    float v  = Fin[(size_t)zi * 1024 + t];
    float sq = v * v;
#pragma unroll
    for (int o = 16; o; o >>= 1) sq += __shfl_xor_sync(0xffffffffu, sq, o);
    if (lane == 0) wred[w] = sq;
    __syncthreads();
    if (t == 0) {
        float s = 0.f;
#pragma unroll
        for (int q = 0; q < 32; q++) s += wred[q];
        s_scale = rsqrtf(fmaxf(s, 1e-30f));
    }
    __syncthreads();
    X[a][b] = v * s_scale;
    __syncthreads();

    for (int iter = 0; iter < 64; iter++) {
        float s = 0.f;
#pragma unroll
        for (int k = 0; k < 32; k++) s += X[k][a] * X[k][b];   // (X^T X)[a][b]
        bool bad = fabsf(s - ((a == b) ? 1.f : 0.f)) > 2e-5f;
        __syncthreads();
        Sm[a][b] = s;
        if (t == 0) s_flag = 0;
        __syncthreads();
        if (bad) s_flag = 1;
        __syncthreads();
        if (!s_flag) break;                   // converged: X is the polar factor
        float y = 0.f;
#pragma unroll
        for (int k = 0; k < 32; k++) y += X[a][k] * Sm[k][b];
        y = 1.5f * X[a][b] - 0.5f * y;
        __syncthreads();
        X[a][b] = y;
        __syncthreads();
    }
    Fout[(size_t)zi * 1024 + t] = X[a][b];
}

// ======================= 11) total_hol reduction ============================
__global__ __launch_bounds__(1024) void total_kernel(
    const float* __restrict__ rowpart, float* __restrict__ outv)
{
    __shared__ float wred[32];
    int t = threadIdx.x, lane = t & 31, w = t >> 5;
    float s = rowpart[t] + rowpart[t + 1024] + rowpart[t + 2048] + rowpart[t + 3072];
#pragma unroll
    for (int o = 16; o; o >>= 1) s += __shfl_xor_sync(0xffffffffu, s, o);
    if (lane == 0) wred[w] = s;
    __syncthreads();
    if (t == 0) {
        float tot = 0.f;
#pragma unroll
        for (int q = 0; q < 32; q++) tot += wred[q];
        *outv = tot;
    }
}

// ======================= launcher ===========================================
extern "C" void kernel_launch(void* const* d_in, const int* in_sizes, int n_in,
                              void* d_out, int out_size)
{
    const float* base  = (const float*)d_in[0];
    const float* fiber = (const float*)d_in[1];
    const float* conn  = (const float*)d_in[2];
    const float* gen   = (const float*)d_in[3];
    const float* Wq    = (const float*)d_in[4];
    const float* bq    = (const float*)d_in[5];
    const float* Wk    = (const float*)d_in[6];
    const float* bk    = (const float*)d_in[7];
    const float* Wv    = (const float*)d_in[8];
    const float* bv    = (const float*)d_in[9];
    const float* Wo    = (const float*)d_in[10];
    const float* bo    = (const float*)d_in[11];
    const float* lam   = (const float*)d_in[12];
    float* out = (float*)d_out;

    float* sc;
    cudaGetSymbolAddress((void**)&sc, g_scratch);
    float* M       = sc;
    float* hol     = M + 524288;
    float* Q       = hol + 131072;
    float* Km      = Q + 262144;
    float* V       = Km + 262144;
    float* attn    = V + 262144;
    float* avg     = attn + 1048576;
    float* outpre  = avg + 131072;
    float* fpre    = outpre + 262144;
    float* rowpart = fpre + 524288;

    // 1) expm + M
    expm_kernel<<<512, 1024>>>(conn, gen, M);

    // 2) holonomy (upper triangle, written symmetric)
    hol_kernel<<<dim3(64, 256, 2), 128>>>(M, hol);

    // 3) Q/K/V projections  (512x512x512)
    sgemm_nn<<<dim3(8, 8, 1), 256>>>(base, Wq, bq, Q, 512, 512, 512, 512, 1, 0, 0, 0, 0, 0, 0);
    sgemm_nn<<<dim3(8, 8, 1), 256>>>(base, Wk, bk, Km, 512, 512, 512, 512, 1, 0, 0, 0, 0, 0, 0);
    sgemm_nn<<<dim3(8, 8, 1), 256>>>(base, Wv, bv, V, 512, 512, 512, 512, 1, 0, 0, 0, 0, 0, 0);

    // 4) scores (fused scale + hol bias)
    scores_kernel<<<dim3(4, 4, 16), 256>>>(Q, Km, hol, lam, attn);

    // 5) softmax (+ total_hol row partials)
    softmax_kernel<<<4096, 256>>>(attn, hol, rowpart);

    // 6) attn @ V  -> outpre   (batched over z,h: M=256,N=64,K=256)
    sgemm_nn<<<dim3(1, 4, 16), 256>>>(attn, V, nullptr, outpre,
                                      256, 256, 512, 512, 8,
                                      524288, 65536, 131072, 64, 131072, 64);

    // 7) @ Wo + bo -> out
    sgemm_nn<<<dim3(8, 8, 1), 256>>>(outpre, Wo, bo, out, 512, 512, 512, 512, 1, 0, 0, 0, 0, 0, 0);

    // 8) avg over heads
    avg_kernel<<<512, 256>>>(attn, avg);

    // 9) avg_attn @ fiber -> fpre   (batched over z: M=256,N=1024,K=256)
    sgemm_nn<<<dim3(16, 4, 2), 256>>>(avg, fiber, nullptr, fpre,
                                      256, 256, 1024, 1024, 1,
                                      65536, 0, 262144, 0, 262144, 0);

    // 10) polar projection -> new_fiber
    ns_kernel<<<512, 1024>>>(fpre, out + 262144);

    // 11) total_hol
    total_kernel<<<1, 1024>>>(rowpart, out + 786432);
}

// round 3
// speedup vs baseline: 1.0842x; 1.0842x over previous
#include <cuda_runtime.h>
#include <cuda_bf16.h>

// ---------------------------------------------------------------------------
// ParallelTransportAttention  (B=2, S=256, D=512, H=8, Dh=64, df=32, rank=8)
// Round 3: R2 design with 16B-aligned smem padding (68-float rows)
// ---------------------------------------------------------------------------

__device__ __align__(256) float g_scratch[3411968];

// ======================= 1) matrix exponential + M ==========================
__global__ __launch_bounds__(1024) void expm_kernel(
    const float* __restrict__ conn, const float* __restrict__ gen,
    float* __restrict__ Mout)
{
    __shared__ float sA[32][33], sP[32][33], sT[32][33], sW[32][33];
    __shared__ float scol[32];
    __shared__ int   s_s;
    int zs = blockIdx.x;            // 0..511
    int t  = threadIdx.x;           // 0..1023
    int a = t >> 5, b = t & 31;

    const float* c8 = conn + zs * 8;
    float acc = 0.f;
#pragma unroll
    for (int r = 0; r < 8; r++) acc += c8[r] * gen[r * 1024 + t];
    acc *= 0.1f;
    sA[a][b] = acc;
    sW[a][b] = fabsf(acc);
    __syncthreads();

    if (t < 32) {
        float cs = 0.f;
#pragma unroll
        for (int q = 0; q < 32; q++) cs += sW[q][t];
        scol[t] = cs;
    }
    __syncthreads();
    if (t == 0) {
        float nrm = 0.f;
#pragma unroll
        for (int q = 0; q < 32; q++) nrm = fmaxf(nrm, scol[q]);
        int s = 0;
        while (nrm > 0.25f * exp2f((float)s) && s < 12) s++;
        s_s = s;
    }
    __syncthreads();
    int   s  = s_s;
    float sc = exp2f((float)(-s));
    float aab = sA[a][b] * sc;
    __syncthreads();
    sA[a][b] = aab;
    sP[a][b] = aab;
    sT[a][b] = aab + ((a == b) ? 1.f : 0.f);
    __syncthreads();

    for (int k = 2; k <= 9; k++) {
        float d = 0.f;
#pragma unroll
        for (int j = 0; j < 32; j++) d += sP[a][j] * sA[j][b];
        d *= (1.f / (float)k);
        __syncthreads();
        sP[a][b] = d;
        sT[a][b] += d;
        __syncthreads();
    }
    for (int it = 0; it < s; it++) {
        float d = 0.f;
#pragma unroll
        for (int j = 0; j < 32; j++) d += sT[a][j] * sT[j][b];
        __syncthreads();
        sT[a][b] = d;
        __syncthreads();
    }
    float m = 0.f;
#pragma unroll
    for (int k2 = 0; k2 < 32; k2++) m += sT[k2][a] * sT[k2][b];
    Mout[zs * 1024 + t] = m;
}

// ======================= 2) pairwise holonomy (triangular grid) =============
__global__ __launch_bounds__(128) void hol_kernel(
    const float* __restrict__ Mg, float* __restrict__ hol)
{
    __shared__ float sMi[32][32];
    __shared__ float sP[4][32][33];
    int tlin = blockIdx.x;                 // 0..8319
    int z    = blockIdx.y;
    int t = threadIdx.x;
    int w = t >> 5, lane = t & 31;

    // decode triangular tile index: C(g) = 258g - 2g^2
    int g = (int)((258.0 - sqrt(66564.0 - 8.0 * (double)tlin)) * 0.25);
    if (g > 63) g = 63;
    if (g < 0) g = 0;
    while (258 * g - 2 * g * g > tlin) g--;
    while (258 * (g + 1) - 2 * (g + 1) * (g + 1) <= tlin) g++;
    int rem = tlin - (258 * g - 2 * g * g);
    int per = 64 - g;
    int i  = 4 * g + rem / per;
    int jt = g + rem % per;

    const float4* mi4  = (const float4*)(Mg + (size_t)(z * 256 + i) * 1024);
    float4*       sMiv = (float4*)&sMi[0][0];
    for (int q = t; q < 256; q += 128) sMiv[q] = mi4[q];
    __syncthreads();

    int j = jt * 4 + w;
    if (j < i) return;
    if (j == i) {
        if (lane == 0) hol[((size_t)(z * 256 + i)) * 256 + i] = 0.f;
        return;
    }

    float mj[32];
    const float4* mj4 = (const float4*)(Mg + (size_t)(z * 256 + j) * 1024 + lane * 32);
#pragma unroll
    for (int q = 0; q < 8; q++) {
        float4 v = mj4[q];
        mj[4*q] = v.x; mj[4*q+1] = v.y; mj[4*q+2] = v.z; mj[4*q+3] = v.w;
    }

    float p[32];
    float t1 = 0.f;
    const float4* smi4 = (const float4*)&sMi[0][0];
#pragma unroll
    for (int a2 = 0; a2 < 32; a2++) {
        float acc = 0.f;
#pragma unroll
        for (int q = 0; q < 8; q++) {
            float4 m = smi4[a2 * 8 + q];     // broadcast
            acc += m.x * mj[4*q] + m.y * mj[4*q+1] + m.z * mj[4*q+2] + m.w * mj[4*q+3];
        }
        p[a2] = acc;
        sP[w][a2][lane] = acc;
        if (a2 == lane) t1 = acc;
    }
    __syncwarp();
    float t2 = 0.f;
#pragma unroll
    for (int a2 = 0; a2 < 32; a2++) t2 += p[a2] * sP[w][lane][a2];

#pragma unroll
    for (int off = 16; off; off >>= 1) {
        t1 += __shfl_down_sync(0xffffffffu, t1, off);
        t2 += __shfl_down_sync(0xffffffffu, t2, off);
    }
    if (lane == 0) {
        float h2 = t2 - 2.f * t1 + 32.f;
        float h  = sqrtf(fmaxf(h2, 0.f));
        hol[((size_t)(z * 256 + i)) * 256 + j] = h;
        hol[((size_t)(z * 256 + j)) * 256 + i] = h;
    }
}

// ======================= double-buffered 64x64 GEMM core ====================
// NN GEMM mainloop: TK=32 chunks, one __syncthreads per chunk.
// As/Bs rows padded to 68 floats (16B-aligned for float4 smem reads).

#define GEMM_LOOP_NN(Atile, Btile, lda, ldb, NC)                               \
    {                                                                          \
        int arow = t >> 2, acol = (t & 3) * 8;                                 \
        int brow = t >> 3, bcol = (t & 7) * 8;                                 \
        float4 a0 = *(const float4*)((Atile) + (long)arow * (lda) + acol);     \
        float4 a1 = *(const float4*)((Atile) + (long)arow * (lda) + acol + 4); \
        float4 b0 = *(const float4*)((Btile) + (long)brow * (ldb) + bcol);     \
        float4 b1 = *(const float4*)((Btile) + (long)brow * (ldb) + bcol + 4); \
        As[0][acol+0][arow]=a0.x; As[0][acol+1][arow]=a0.y;                    \
        As[0][acol+2][arow]=a0.z; As[0][acol+3][arow]=a0.w;                    \
        As[0][acol+4][arow]=a1.x; As[0][acol+5][arow]=a1.y;                    \
        As[0][acol+6][arow]=a1.z; As[0][acol+7][arow]=a1.w;                    \
        *(float4*)&Bs[0][brow][bcol]   = b0;                                   \
        *(float4*)&Bs[0][brow][bcol+4] = b1;                                   \
        __syncthreads();                                                       \
        for (int c = 0; c < (NC); c++) {                                       \
            int cur = c & 1;                                                   \
            if (c + 1 < (NC)) {                                                \
                const float* Ap = (Atile) + (c + 1) * 32;                      \
                const float* Bp = (Btile) + (long)(c + 1) * 32 * (ldb);        \
                a0 = *(const float4*)(Ap + (long)arow * (lda) + acol);         \
                a1 = *(const float4*)(Ap + (long)arow * (lda) + acol + 4);     \
                b0 = *(const float4*)(Bp + (long)brow * (ldb) + bcol);         \
                b1 = *(const float4*)(Bp + (long)brow * (ldb) + bcol + 4);     \
            }                                                                  \
            _Pragma("unroll")                                                  \
            for (int k = 0; k < 32; k++) {                                     \
                float4 a4 = *(const float4*)&As[cur][k][ty * 4];               \
                float4 b4 = *(const float4*)&Bs[cur][k][tx * 4];               \
                acc[0][0] += a4.x*b4.x; acc[0][1] += a4.x*b4.y;                \
                acc[0][2] += a4.x*b4.z; acc[0][3] += a4.x*b4.w;                \
                acc[1][0] += a4.y*b4.x; acc[1][1] += a4.y*b4.y;                \
                acc[1][2] += a4.y*b4.z; acc[1][3] += a4.y*b4.w;                \
                acc[2][0] += a4.z*b4.x; acc[2][1] += a4.z*b4.y;                \
                acc[2][2] += a4.z*b4.z; acc[2][3] += a4.z*b4.w;                \
                acc[3][0] += a4.w*b4.x; acc[3][1] += a4.w*b4.y;                \
                acc[3][2] += a4.w*b4.z; acc[3][3] += a4.w*b4.w;                \
            }                                                                  \
            if (c + 1 < (NC)) {                                                \
                int nxt = cur ^ 1;                                             \
                As[nxt][acol+0][arow]=a0.x; As[nxt][acol+1][arow]=a0.y;        \
                As[nxt][acol+2][arow]=a0.z; As[nxt][acol+3][arow]=a0.w;        \
                As[nxt][acol+4][arow]=a1.x; As[nxt][acol+5][arow]=a1.y;        \
                As[nxt][acol+6][arow]=a1.z; As[nxt][acol+7][arow]=a1.w;        \
                *(float4*)&Bs[nxt][brow][bcol]   = b0;                         \
                *(float4*)&Bs[nxt][brow][bcol+4] = b1;                         \
            }                                                                  \
            __syncthreads();                                                   \
        }                                                                      \
    }

// ======================= 3) fused QKV projections ===========================
__global__ __launch_bounds__(256) void qkv_kernel(
    const float* __restrict__ base,
    const float* __restrict__ Wq, const float* __restrict__ Wk, const float* __restrict__ Wv,
    const float* __restrict__ bq, const float* __restrict__ bk, const float* __restrict__ bv,
    float* __restrict__ Qo, float* __restrict__ Ko, float* __restrict__ Vo)
{
    __shared__ float As[2][32][68];
    __shared__ float Bs[2][32][68];
    int which = blockIdx.z;
    const float* W    = (which == 0) ? Wq : (which == 1) ? Wk : Wv;
    const float* bias = (which == 0) ? bq : (which == 1) ? bk : bv;
    float*       C    = (which == 0) ? Qo : (which == 1) ? Ko : Vo;

    int t  = threadIdx.x;
    int tx = t & 15, ty = t >> 4;
    int row0 = blockIdx.y * 64, col0 = blockIdx.x * 64;
    const float* Atile = base + (long)row0 * 512;
    const float* Btile = W + col0;

    float acc[4][4] = {};
    GEMM_LOOP_NN(Atile, Btile, 512, 512, 16);

    float bv4[4];
#pragma unroll
    for (int j = 0; j < 4; j++) bv4[j] = bias[col0 + tx * 4 + j];
#pragma unroll
    for (int ii = 0; ii < 4; ii++) {
        float4 o;
        o.x = acc[ii][0] + bv4[0]; o.y = acc[ii][1] + bv4[1];
        o.z = acc[ii][2] + bv4[2]; o.w = acc[ii][3] + bv4[3];
        *(float4*)(C + (long)(row0 + ty * 4 + ii) * 512 + col0 + tx * 4) = o;
    }
}

// ======================= generic strided-batched SGEMM (NN) =================
__global__ __launch_bounds__(256) void sgemm_nn(
    const float* __restrict__ A, const float* __restrict__ B,
    const float* __restrict__ bias, float* __restrict__ C,
    int K, int lda, int ldb, int ldc, int bdiv,
    long sA1, long sA2, long sB1, long sB2, long sC1, long sC2)
{
    __shared__ float As[2][32][68];
    __shared__ float Bs[2][32][68];
    int bz = blockIdx.z;
    A += (long)(bz / bdiv) * sA1 + (long)(bz % bdiv) * sA2;
    B += (long)(bz / bdiv) * sB1 + (long)(bz % bdiv) * sB2;
    C += (long)(bz / bdiv) * sC1 + (long)(bz % bdiv) * sC2;

    int t  = threadIdx.x;
    int tx = t & 15, ty = t >> 4;
    int row0 = blockIdx.y * 64, col0 = blockIdx.x * 64;
    const float* Atile = A + (long)row0 * lda;
    const float* Btile = B + col0;
    int NC = K >> 5;

    float acc[4][4] = {};
    GEMM_LOOP_NN(Atile, Btile, lda, ldb, NC);

    float bv4[4] = {0.f, 0.f, 0.f, 0.f};
    if (bias) {
#pragma unroll
        for (int j = 0; j < 4; j++) bv4[j] = bias[col0 + tx * 4 + j];
    }
#pragma unroll
    for (int ii = 0; ii < 4; ii++) {
        float4 o;
        o.x = acc[ii][0] + bv4[0]; o.y = acc[ii][1] + bv4[1];
        o.z = acc[ii][2] + bv4[2]; o.w = acc[ii][3] + bv4[3];
        *(float4*)(C + (long)(row0 + ty * 4 + ii) * ldc + col0 + tx * 4) = o;
    }
}

// ======================= 4) scores = QK^T/8 - lambda*hol (NT) ===============
__global__ __launch_bounds__(256) void scores_kernel(
    const float* __restrict__ Qm, const float* __restrict__ Km,
    const float* __restrict__ hol, const float* __restrict__ lam,
    float* __restrict__ Sout)
{
    __shared__ float As[2][32][68];
    __shared__ float Bs[2][32][68];
    int zh = blockIdx.z, z = zh >> 3, h = zh & 7;
    int t  = threadIdx.x;
    int tx = t & 15, ty = t >> 4;
    int i0 = blockIdx.y * 64, j0 = blockIdx.x * 64;
    const float* Atile = Qm + (long)z * 131072 + h * 64 + (long)i0 * 512;
    const float* Btile = Km + (long)z * 131072 + h * 64 + (long)j0 * 512;

    int arow = t >> 2, acol = (t & 3) * 8;
    float acc[4][4] = {};

    // preload chunk 0 (K = 64 -> 2 chunks)
    float4 a0 = *(const float4*)(Atile + (long)arow * 512 + acol);
    float4 a1 = *(const float4*)(Atile + (long)arow * 512 + acol + 4);
    float4 b0 = *(const float4*)(Btile + (long)arow * 512 + acol);
    float4 b1 = *(const float4*)(Btile + (long)arow * 512 + acol + 4);
    As[0][acol+0][arow]=a0.x; As[0][acol+1][arow]=a0.y;
    As[0][acol+2][arow]=a0.z; As[0][acol+3][arow]=a0.w;
    As[0][acol+4][arow]=a1.x; As[0][acol+5][arow]=a1.y;
    As[0][acol+6][arow]=a1.z; As[0][acol+7][arow]=a1.w;
    Bs[0][acol+0][arow]=b0.x; Bs[0][acol+1][arow]=b0.y;
    Bs[0][acol+2][arow]=b0.z; Bs[0][acol+3][arow]=b0.w;
    Bs[0][acol+4][arow]=b1.x; Bs[0][acol+5][arow]=b1.y;
    Bs[0][acol+6][arow]=b1.z; Bs[0][acol+7][arow]=b1.w;
    __syncthreads();
    for (int c = 0; c < 2; c++) {
        int cur = c & 1;
        if (c == 0) {
            a0 = *(const float4*)(Atile + (long)arow * 512 + 32 + acol);
            a1 = *(const float4*)(Atile + (long)arow * 512 + 32 + acol + 4);
            b0 = *(const float4*)(Btile + (long)arow * 512 + 32 + acol);
            b1 = *(const float4*)(Btile + (long)arow * 512 + 32 + acol + 4);
        }
#pragma unroll
        for (int k = 0; k < 32; k++) {
            float4 a4 = *(const float4*)&As[cur][k][ty * 4];
            float4 b4 = *(const float4*)&Bs[cur][k][tx * 4];
            acc[0][0] += a4.x*b4.x; acc[0][1] += a4.x*b4.y; acc[0][2] += a4.x*b4.z; acc[0][3] += a4.x*b4.w;
            acc[1][0] += a4.y*b4.x; acc[1][1] += a4.y*b4.y; acc[1][2] += a4.y*b4.z; acc[1][3] += a4.y*b4.w;
            acc[2][0] += a4.z*b4.x; acc[2][1] += a4.z*b4.y; acc[2][2] += a4.z*b4.z; acc[2][3] += a4.z*b4.w;
            acc[3][0] += a4.w*b4.x; acc[3][1] += a4.w*b4.y; acc[3][2] += a4.w*b4.z; acc[3][3] += a4.w*b4.w;
        }
        if (c == 0) {
            As[1][acol+0][arow]=a0.x; As[1][acol+1][arow]=a0.y;
            As[1][acol+2][arow]=a0.z; As[1][acol+3][arow]=a0.w;
            As[1][acol+4][arow]=a1.x; As[1][acol+5][arow]=a1.y;
            As[1][acol+6][arow]=a1.z; As[1][acol+7][arow]=a1.w;
            Bs[1][acol+0][arow]=b0.x; Bs[1][acol+1][arow]=b0.y;
            Bs[1][acol+2][arow]=b0.z; Bs[1][acol+3][arow]=b0.w;
            Bs[1][acol+4][arow]=b1.x; Bs[1][acol+5][arow]=b1.y;
            Bs[1][acol+6][arow]=b1.z; Bs[1][acol+7][arow]=b1.w;
        }
        __syncthreads();
    }

    float l = __ldg(lam);
#pragma unroll
    for (int ii = 0; ii < 4; ii++) {
        int irow = i0 + ty * 4 + ii;
#pragma unroll
        for (int jj = 0; jj < 4; jj++) {
            int jcol = j0 + tx * 4 + jj;
            float v = acc[ii][jj] * 0.125f
                    - l * hol[((size_t)(z * 256 + irow)) * 256 + jcol];
            Sout[(size_t)zh * 65536 + (size_t)irow * 256 + jcol] = v;
        }
    }
}

// ======================= 5) softmax + hol partials ==========================
__global__ __launch_bounds__(256) void softmax_kernel(
    float* __restrict__ Sm, const float* __restrict__ hol,
    float* __restrict__ rowpart)
{
    __shared__ float red[8];
    __shared__ float bval;
    int row = blockIdx.x;
    int z = row >> 11;
    int i = row & 255;
    int t = threadIdx.x;
    int w = t >> 5, lane = t & 31;

    float v = Sm[(size_t)row * 256 + t];
    float m = v;
#pragma unroll
    for (int o = 16; o; o >>= 1) m = fmaxf(m, __shfl_xor_sync(0xffffffffu, m, o));
    if (lane == 0) red[w] = m;
    __syncthreads();
    if (t == 0) {
        float mm = red[0];
#pragma unroll
        for (int q = 1; q < 8; q++) mm = fmaxf(mm, red[q]);
        bval = mm;
    }
    __syncthreads();
    float e  = expf(v - bval);
    float ss = e;
#pragma unroll
    for (int o = 16; o; o >>= 1) ss += __shfl_xor_sync(0xffffffffu, ss, o);
    __syncthreads();
    if (lane == 0) red[w] = ss;
    __syncthreads();
    if (t == 0) {
        float s2 = 0.f;
#pragma unroll
        for (int q = 0; q < 8; q++) s2 += red[q];
        bval = s2;
    }
    __syncthreads();
    float at = e / bval;
    Sm[(size_t)row * 256 + t] = at;

    float hp = at * hol[((size_t)(z * 256 + i)) * 256 + t];
#pragma unroll
    for (int o = 16; o; o >>= 1) hp += __shfl_xor_sync(0xffffffffu, hp, o);
    __syncthreads();
    if (lane == 0) red[w] = hp;
    __syncthreads();
    if (t == 0) {
        float s3 = 0.f;
#pragma unroll
        for (int q = 0; q < 8; q++) s3 += red[q];
        rowpart[row] = s3;
    }
}

// ======================= 8) head-average of attn ============================
__global__ __launch_bounds__(256) void avg_kernel(
    const float* __restrict__ attn, float* __restrict__ avg)
{
    size_t idx = (size_t)blockIdx.x * 256 + threadIdx.x;
    size_t z  = idx >> 16;
    size_t ij = idx & 65535;
    float s = 0.f;
#pragma unroll
    for (int h = 0; h < 8; h++) s += attn[(z * 8 + h) * 65536 + ij];
    avg[idx] = s * 0.125f;
}

// ======================= 10) Newton-Schulz polar factor =====================
__global__ __launch_bounds__(1024) void ns_kernel(
    const float* __restrict__ Fin, float* __restrict__ Fout)
{
    __shared__ float X[32][33], Sm[32][33];
    __shared__ float wred[32];
    __shared__ float s_scale;
    __shared__ int   s_flag;
    int zi = blockIdx.x;
    int t  = threadIdx.x;
    int a = t >> 5, b = t & 31, lane = t & 31, w = t >> 5;

    float v  = Fin[(size_t)zi * 1024 + t];
    float sq = v * v;
#pragma unroll
    for (int o = 16; o; o >>= 1) sq += __shfl_xor_sync(0xffffffffu, sq, o);
    if (lane == 0) wred[w] = sq;
    __syncthreads();
    if (t == 0) {
        float s = 0.f;
#pragma unroll
        for (int q = 0; q < 32; q++) s += wred[q];
        s_scale = rsqrtf(fmaxf(s, 1e-30f));
    }
    __syncthreads();
    X[a][b] = v * s_scale;
    __syncthreads();

    for (int iter = 0; iter < 64; iter++) {
        float s = 0.f;
#pragma unroll
        for (int k = 0; k < 32; k++) s += X[k][a] * X[k][b];
        bool bad = fabsf(s - ((a == b) ? 1.f : 0.f)) > 2e-5f;
        __syncthreads();
        Sm[a][b] = s;
        if (t == 0) s_flag = 0;
        __syncthreads();
        if (bad) s_flag = 1;
        __syncthreads();
        if (!s_flag) break;
        float y = 0.f;
#pragma unroll
        for (int k = 0; k < 32; k++) y += X[a][k] * Sm[k][b];
        y = 1.5f * X[a][b] - 0.5f * y;
        __syncthreads();
        X[a][b] = y;
        __syncthreads();
    }
    Fout[(size_t)zi * 1024 + t] = X[a][b];
}

// ======================= 11) total_hol reduction ============================
__global__ __launch_bounds__(1024) void total_kernel(
    const float* __restrict__ rowpart, float* __restrict__ outv)
{
    __shared__ float wred[32];
    int t = threadIdx.x, lane = t & 31, w = t >> 5;
    float s = rowpart[t] + rowpart[t + 1024] + rowpart[t + 2048] + rowpart[t + 3072];
#pragma unroll
    for (int o = 16; o; o >>= 1) s += __shfl_xor_sync(0xffffffffu, s, o);
    if (lane == 0) wred[w] = s;
    __syncthreads();
    if (t == 0) {
        float tot = 0.f;
#pragma unroll
        for (int q = 0; q < 32; q++) tot += wred[q];
        *outv = tot;
    }
}

// ======================= launcher ===========================================
extern "C" void kernel_launch(void* const* d_in, const int* in_sizes, int n_in,
                              void* d_out, int out_size)
{
    const float* base  = (const float*)d_in[0];
    const float* fiber = (const float*)d_in[1];
    const float* conn  = (const float*)d_in[2];
    const float* gen   = (const float*)d_in[3];
    const float* Wq    = (const float*)d_in[4];
    const float* bq    = (const float*)d_in[5];
    const float* Wk    = (const float*)d_in[6];
    const float* bk    = (const float*)d_in[7];
    const float* Wv    = (const float*)d_in[8];
    const float* bv    = (const float*)d_in[9];
    const float* Wo    = (const float*)d_in[10];
    const float* bo    = (const float*)d_in[11];
    const float* lam   = (const float*)d_in[12];
    float* out = (float*)d_out;

    float* sc;
    cudaGetSymbolAddress((void**)&sc, g_scratch);
    float* M       = sc;
    float* hol     = M + 524288;
    float* Q       = hol + 131072;
    float* Km      = Q + 262144;
    float* V       = Km + 262144;
    float* attn    = V + 262144;
    float* avg     = attn + 1048576;
    float* outpre  = avg + 131072;
    float* fpre    = outpre + 262144;
    float* rowpart = fpre + 524288;

    // 1) expm + M
    expm_kernel<<<512, 1024>>>(conn, gen, M);

    // 2) holonomy (triangular grid: 8320 tiles per batch)
    hol_kernel<<<dim3(8320, 2), 128>>>(M, hol);

    // 3) fused Q/K/V projections (192 CTAs)
    qkv_kernel<<<dim3(8, 8, 3), 256>>>(base, Wq, Wk, Wv, bq, bk, bv, Q, Km, V);

    // 4) scores (fused scale + hol bias)
    scores_kernel<<<dim3(4, 4, 16), 256>>>(Q, Km, hol, lam, attn);

    // 5) softmax (+ total_hol row partials)
    softmax_kernel<<<4096, 256>>>(attn, hol, rowpart);

    // 6) attn @ V  -> outpre
    sgemm_nn<<<dim3(1, 4, 16), 256>>>(attn, V, nullptr, outpre,
                                      256, 256, 512, 512, 8,
                                      524288, 65536, 131072, 64, 131072, 64);

    // 7) @ Wo + bo -> out
    sgemm_nn<<<dim3(8, 8, 1), 256>>>(outpre, Wo, bo, out, 512, 512, 512, 512, 1, 0, 0, 0, 0, 0, 0);

    // 8) avg over heads
    avg_kernel<<<512, 256>>>(attn, avg);

    // 9) avg_attn @ fiber -> fpre
    sgemm_nn<<<dim3(16, 4, 2), 256>>>(avg, fiber, nullptr, fpre,
                                      256, 256, 1024, 1024, 1,
                                      65536, 0, 262144, 0, 262144, 0);

    // 10) polar projection -> new_fiber
    ns_kernel<<<512, 1024>>>(fpre, out + 262144);

    // 11) total_hol
    total_kernel<<<1, 1024>>>(rowpart, out + 786432);
}